// round 7
// baseline (speedup 1.0000x reference)
#include <cuda_runtime.h>
#include <cuda_bf16.h>
#include <math.h>
#include <stdint.h>

#define N_NODES 50000
#define N_EDGES 800000
#define N_GRAPHS 100

// ---------------- device scratch (no allocation allowed; 16B aligned) ----------------
__device__ __align__(16) int   d_cnt[N_NODES];      // stays 0 between calls (re-zeroed by pool_mlp)
__device__ __align__(16) float d_dinv[N_NODES];
__device__ __align__(16) int   d_off[N_NODES];
__device__ __align__(16) int   d_cursor[N_NODES];
__device__ __align__(16) int   d_src[N_EDGES];
__device__ int d_gcur;                               // stays 0 between calls
__device__ __align__(16) float d_t[(size_t)N_NODES * 128];
__device__ __align__(16) float d_h[(size_t)N_NODES * 128];

// ---------------- packed f32x2 helpers ----------------
__device__ __forceinline__ unsigned long long pk2(float x) {
    unsigned long long r;
    asm("mov.b64 %0, {%1, %1};" : "=l"(r) : "r"(__float_as_uint(x)));
    return r;
}
#define FMA2(acc, a, b) \
    asm("fma.rn.f32x2 %0, %1, %2, %0;" : "+l"(acc) : "l"(a), "l"(b))
#define MUL2(d, a, b) \
    asm("mul.rn.f32x2 %0, %1, %2;" : "=l"(d) : "l"(a), "l"(b))

// ---------------- CSR build (scan-free) ----------------
__global__ void count_kernel(const int* __restrict__ col, int* __restrict__ cnt) {
    int e2 = blockIdx.x * blockDim.x + threadIdx.x;
    int e = e2 * 2;
    if (e + 1 < N_EDGES) {
        int2 c = *reinterpret_cast<const int2*>(col + e);
        if ((unsigned)c.x < N_NODES) atomicAdd(cnt + c.x, 1);
        if ((unsigned)c.y < N_NODES) atomicAdd(cnt + c.y, 1);
    } else if (e < N_EDGES) {
        unsigned c = (unsigned)col[e];
        if (c < N_NODES) atomicAdd(cnt + c, 1);
    }
}

// per-block scan + one atomic bump for the block's base; segments disjoint,
// ordering across blocks irrelevant. Also computes dinv.
__global__ void assign_kernel(const int* __restrict__ cnt, int* __restrict__ off,
                              int* __restrict__ cursor, float* __restrict__ dinv,
                              int* __restrict__ gcur) {
    __shared__ int ws[32];
    __shared__ int s_base;
    int i = blockIdx.x * 1024 + threadIdx.x;
    int lane = threadIdx.x & 31, wid = threadIdx.x >> 5;
    int v = (i < N_NODES) ? cnt[i] : 0;
    int x = v;
    #pragma unroll
    for (int d = 1; d < 32; d <<= 1) {
        int y = __shfl_up_sync(0xffffffffu, x, d);
        if (lane >= d) x += y;
    }
    if (lane == 31) ws[wid] = x;
    __syncthreads();
    if (wid == 0) {
        int s = ws[lane];
        #pragma unroll
        for (int d = 1; d < 32; d <<= 1) {
            int y = __shfl_up_sync(0xffffffffu, s, d);
            if (lane >= d) s += y;
        }
        ws[lane] = s;
        if (lane == 31) s_base = atomicAdd(gcur, s);
    }
    __syncthreads();
    int excl = s_base + (wid ? ws[wid - 1] : 0) + x - v;
    if (i < N_NODES) {
        off[i] = excl;
        cursor[i] = excl;
        dinv[i] = rsqrtf((float)(v + 1));
    }
}

__global__ void fill_kernel(const int* __restrict__ row,
                            const int* __restrict__ col,
                            int* __restrict__ cursor, int* __restrict__ src) {
    int e2 = blockIdx.x * blockDim.x + threadIdx.x;
    int e = e2 * 2;
    if (e + 1 < N_EDGES) {
        int2 c = *reinterpret_cast<const int2*>(col + e);
        int2 r = *reinterpret_cast<const int2*>(row + e);
        if ((unsigned)c.x < N_NODES) {
            int pos = atomicAdd(cursor + c.x, 1);
            if ((unsigned)pos < N_EDGES) src[pos] = r.x;
        }
        if ((unsigned)c.y < N_NODES) {
            int pos = atomicAdd(cursor + c.y, 1);
            if ((unsigned)pos < N_EDGES) src[pos] = r.y;
        }
    } else if (e < N_EDGES) {
        unsigned c = (unsigned)col[e];
        if (c < N_NODES) {
            int pos = atomicAdd(cursor + c, 1);
            if ((unsigned)pos < N_EDGES) src[pos] = row[e];
        }
    }
}

// ---------------- persistent-W GEMM: T[v] = dinv[v] * (A[v] @ W) ----------------
// W resident in SMEM per CTA; BM=32 row tiles streamed with double buffer.
// 256 threads: thread tile = 2 rows x (NOUT/16) cols.
template <int NOUT>
__global__ void __launch_bounds__(256, 2)
gemm_pw_kernel(const float* __restrict__ A, const float* __restrict__ W,
               const float* __restrict__ dinv, float* __restrict__ T,
               int ntiles, int grid) {
    constexpr int CW  = NOUT / 16;        // cols per thread: 8 or 4
    constexpr int TNP = CW / 2;           // f32x2 pairs: 4 or 2
    extern __shared__ __align__(16) float smem[];
    float* Ws  = smem;                    // [128][NOUT]
    float* As0 = smem + 128 * NOUT;       // [128][32] k-major
    float* As1 = As0 + 128 * 32;
    int tid = threadIdx.x;

    // load W once (row-major [128][NOUT])
    for (int i = tid; i < 128 * NOUT / 4; i += 256)
        reinterpret_cast<float4*>(Ws)[i] = reinterpret_cast<const float4*>(W)[i];

    // A prefetch mapping: lr = row in tile, kg = k-group of 16
    int lr = tid & 31, kg = tid >> 5;           // kg 0..7
    int tx = tid & 15, ty = tid >> 4;           // compute mapping
    int r0 = ty * 2, c0 = tx * CW;

    int tile = blockIdx.x;
    float4 pre[4];
    {
        int gr = tile * 32 + lr;
        #pragma unroll
        for (int j = 0; j < 4; j++)
            pre[j] = (gr < N_NODES)
                ? *reinterpret_cast<const float4*>(A + (size_t)gr * 128 + kg * 16 + j * 4)
                : make_float4(0.f, 0.f, 0.f, 0.f);
    }
    // stage first tile into As0
    #pragma unroll
    for (int j = 0; j < 4; j++) {
        int kb = kg * 16 + j * 4;
        As0[(kb + 0) * 32 + lr] = pre[j].x;
        As0[(kb + 1) * 32 + lr] = pre[j].y;
        As0[(kb + 2) * 32 + lr] = pre[j].z;
        As0[(kb + 3) * 32 + lr] = pre[j].w;
    }
    __syncthreads();

    int buf = 0;
    while (tile < ntiles) {
        int next = tile + grid;
        // prefetch next tile A into regs (latency hidden by compute below)
        if (next < ntiles) {
            int gr = next * 32 + lr;
            #pragma unroll
            for (int j = 0; j < 4; j++)
                pre[j] = (gr < N_NODES)
                    ? *reinterpret_cast<const float4*>(A + (size_t)gr * 128 + kg * 16 + j * 4)
                    : make_float4(0.f, 0.f, 0.f, 0.f);
        }
        const float* As = buf ? As1 : As0;

        unsigned long long acc[2][TNP];
        #pragma unroll
        for (int i = 0; i < 2; i++)
            #pragma unroll
            for (int p = 0; p < TNP; p++) acc[i][p] = 0ULL;

        #pragma unroll 4
        for (int k = 0; k < 128; k++) {
            float2 av = *reinterpret_cast<const float2*>(As + k * 32 + r0);
            unsigned long long ap0 = pk2(av.x), ap1 = pk2(av.y);
            const float* wr = Ws + k * NOUT + c0;
            ulonglong2 u0 = *reinterpret_cast<const ulonglong2*>(wr);
            FMA2(acc[0][0], ap0, u0.x); FMA2(acc[1][0], ap1, u0.x);
            FMA2(acc[0][1], ap0, u0.y); FMA2(acc[1][1], ap1, u0.y);
            if (TNP == 4) {
                ulonglong2 u1 = *reinterpret_cast<const ulonglong2*>(wr + 4);
                FMA2(acc[0][2], ap0, u1.x); FMA2(acc[1][2], ap1, u1.x);
                FMA2(acc[0][3], ap0, u1.y); FMA2(acc[1][3], ap1, u1.y);
            }
        }

        // epilogue: scale by dinv and store
        #pragma unroll
        for (int i = 0; i < 2; i++) {
            int r = tile * 32 + r0 + i;
            if (r < N_NODES) {
                unsigned long long dvp = pk2(dinv[r]);
                unsigned long long o[TNP];
                #pragma unroll
                for (int p = 0; p < TNP; p++) MUL2(o[p], acc[i][p], dvp);
                float* dst = T + (size_t)r * NOUT + c0;
                ulonglong2 s0; s0.x = o[0]; s0.y = o[1];
                *reinterpret_cast<ulonglong2*>(dst) = s0;
                if (TNP == 4) {
                    ulonglong2 s1; s1.x = o[2]; s1.y = o[3];
                    *reinterpret_cast<ulonglong2*>(dst + 4) = s1;
                }
            }
        }

        if (next < ntiles) {
            __syncthreads();   // everyone done reading As[buf] / writing prev
            float* Ad = buf ? As0 : As1;
            #pragma unroll
            for (int j = 0; j < 4; j++) {
                int kb = kg * 16 + j * 4;
                Ad[(kb + 0) * 32 + lr] = pre[j].x;
                Ad[(kb + 1) * 32 + lr] = pre[j].y;
                Ad[(kb + 2) * 32 + lr] = pre[j].z;
                Ad[(kb + 3) * 32 + lr] = pre[j].w;
            }
            __syncthreads();
        }
        buf ^= 1;
        tile = next;
    }
}

// ---------------- aggregation: h[v] = relu(dinv[v]*(t[v] + sum_in t[src]) + b) ----------------
template <int F>
__global__ void agg_kernel(const float* __restrict__ T,
                           const int* __restrict__ off,
                           const int* __restrict__ cnt,
                           const float* __restrict__ dinv,
                           const float* __restrict__ bias,
                           float* __restrict__ H,
                           const int* __restrict__ src) {
    constexpr int V = F / 32;
    int warp = threadIdx.x >> 5, lane = threadIdx.x & 31;
    int v = blockIdx.x * (blockDim.x >> 5) + warp;
    if (v >= N_NODES) return;
    int f0 = lane * V;
    float acc[V];
    #pragma unroll
    for (int i = 0; i < V; i++) acc[i] = T[(size_t)v * F + f0 + i];
    int e0 = off[v], e1 = e0 + cnt[v];
    #pragma unroll 4
    for (int e = e0; e < e1; e++) {
        int s = src[e];
        const float* ts = T + (size_t)s * F + f0;
        #pragma unroll
        for (int i = 0; i < V; i++) acc[i] += ts[i];
    }
    float dv = dinv[v];
    float* hv = H + (size_t)v * F + f0;
    #pragma unroll
    for (int i = 0; i < V; i++) {
        float o = dv * acc[i] + bias[f0 + i];
        hv[i] = fmaxf(o, 0.f);
    }
}

// ---------------- pooling + MLP (+ cleanup of cnt/gcur for next call) ----------------
__device__ __forceinline__ int lb32(const int* __restrict__ b, int n, int key) {
    int lo = 0, hi = n;
    while (lo < hi) {
        int mid = (lo + hi) >> 1;
        if (b[mid] < key) lo = mid + 1; else hi = mid;
    }
    return lo;
}

__global__ void pool_mlp_kernel(const float* __restrict__ H,
                                const int* __restrict__ batch,
                                const float* __restrict__ Wf1, const float* __restrict__ bf1,
                                const float* __restrict__ Wf2, const float* __restrict__ bf2,
                                float* __restrict__ out,
                                int* __restrict__ cnt, int* __restrict__ gcur) {
    __shared__ float partial[256];
    __shared__ float pooled[64];
    __shared__ float hid[32];
    int g = blockIdx.x;
    int t = threadIdx.x;
    // cleanup: restore invariants for next call
    for (int i = g * 256 + t; i < N_NODES; i += N_GRAPHS * 256) cnt[i] = 0;
    if (g == 0 && t == 0) *gcur = 0;

    int start = lb32(batch, N_NODES, g);
    int end   = lb32(batch, N_NODES, g + 1);
    int n = end - start;
    int feat = t & 63;
    int strip = t >> 6;
    float s = 0.f;
    for (int i = start + strip; i < end; i += 4)
        s += H[(size_t)i * 64 + feat];
    partial[t] = s;
    __syncthreads();
    if (t < 64) {
        float tot = partial[t] + partial[t + 64] + partial[t + 128] + partial[t + 192];
        pooled[t] = tot / fmaxf((float)n, 1.0f);
    }
    __syncthreads();
    if (t < 32) {
        float a = bf1[t];
        #pragma unroll 8
        for (int k = 0; k < 64; k++) a += pooled[k] * Wf1[k * 32 + t];
        hid[t] = fmaxf(a, 0.f);
    }
    __syncthreads();
    if (t < 10) {
        float a = bf2[t];
        #pragma unroll
        for (int k = 0; k < 32; k++) a += hid[k] * Wf2[k * 10 + t];
        out[g * 10 + t] = a;
    }
}

// ---------------- launch ----------------
extern "C" void kernel_launch(void* const* d_in, const int* in_sizes, int n_in,
                              void* d_out, int out_size) {
    const float* x     = (const float*)d_in[0];
    const int*   ei    = (const int*)d_in[1];     // int32 (JAX x64 disabled)
    const int*   batch = (const int*)d_in[2];
    const float* W1 = (const float*)d_in[3];
    const float* b1 = (const float*)d_in[4];
    const float* W2 = (const float*)d_in[5];
    const float* b2 = (const float*)d_in[6];
    const float* W3 = (const float*)d_in[7];
    const float* b3 = (const float*)d_in[8];
    const float* Wf1 = (const float*)d_in[9];
    const float* bf1 = (const float*)d_in[10];
    const float* Wf2 = (const float*)d_in[11];
    const float* bf2 = (const float*)d_in[12];
    float* out = (float*)d_out;

    const int* row = ei;
    const int* col = ei + N_EDGES;

    int *p_cnt, *p_off, *p_cursor, *p_src, *p_gcur;
    float *p_dinv, *p_t, *p_h;
    cudaGetSymbolAddress((void**)&p_cnt,    d_cnt);
    cudaGetSymbolAddress((void**)&p_off,    d_off);
    cudaGetSymbolAddress((void**)&p_cursor, d_cursor);
    cudaGetSymbolAddress((void**)&p_src,    d_src);
    cudaGetSymbolAddress((void**)&p_gcur,   d_gcur);
    cudaGetSymbolAddress((void**)&p_dinv,   d_dinv);
    cudaGetSymbolAddress((void**)&p_t,      d_t);
    cudaGetSymbolAddress((void**)&p_h,      d_h);

    const int SM128 = (128 * 128 + 2 * 128 * 32) * 4;   // 96 KB
    const int SM64  = (128 * 64  + 2 * 128 * 32) * 4;   // 64 KB
    cudaFuncSetAttribute(gemm_pw_kernel<128>, cudaFuncAttributeMaxDynamicSharedMemorySize, SM128);
    cudaFuncSetAttribute(gemm_pw_kernel<64>,  cudaFuncAttributeMaxDynamicSharedMemorySize, SM64);

    const int E2 = (N_EDGES / 2 + 255) / 256;
    const int NT = (N_NODES + 31) / 32;      // 1563 row tiles
    const int G128 = 296;                    // 2 CTAs/SM persistent
    const int G64  = 444;                    // 3 CTAs/SM
    const int AGG_BLOCKS = (N_NODES + 7) / 8;

    // CSR build
    count_kernel<<<E2, 256>>>(col, p_cnt);                                           // 1
    assign_kernel<<<(N_NODES + 1023) / 1024, 1024>>>(p_cnt, p_off, p_cursor, p_dinv, p_gcur); // 2
    fill_kernel<<<E2, 256>>>(row, col, p_cursor, p_src);                             // 3

    gemm_pw_kernel<128><<<G128, 256, SM128>>>(x, W1, p_dinv, p_t, NT, G128);         // 4
    agg_kernel<128><<<AGG_BLOCKS, 256>>>(p_t, p_off, p_cnt, p_dinv, b1, p_h, p_src); // 5
    gemm_pw_kernel<128><<<G128, 256, SM128>>>(p_h, W2, p_dinv, p_t, NT, G128);       // 6 <- ncu
    agg_kernel<128><<<AGG_BLOCKS, 256>>>(p_t, p_off, p_cnt, p_dinv, b2, p_h, p_src); // 7
    gemm_pw_kernel<64><<<G64, 256, SM64>>>(p_h, W3, p_dinv, p_t, NT, G64);           // 8
    agg_kernel<64><<<AGG_BLOCKS, 256>>>(p_t, p_off, p_cnt, p_dinv, b3, p_h, p_src);  // 9

    pool_mlp_kernel<<<N_GRAPHS, 256>>>(p_h, batch, Wf1, bf1, Wf2, bf2, out, p_cnt, p_gcur); // 10
}

// round 8
// speedup vs baseline: 2.0433x; 2.0433x over previous
#include <cuda_runtime.h>
#include <cuda_fp16.h>
#include <math.h>
#include <stdint.h>

#define N_NODES 50000
#define N_EDGES 800000
#define N_GRAPHS 100

// ---------------- device scratch (no allocation allowed; 16B aligned) ----------------
__device__ __align__(16) int    d_cnt[N_NODES];      // stays 0 between calls (re-zeroed by pool_mlp)
__device__ __align__(16) float  d_dinv[N_NODES];
__device__ __align__(16) int    d_off[N_NODES];
__device__ __align__(16) int    d_cursor[N_NODES];
__device__ __align__(16) int    d_src[N_EDGES];
__device__ int d_gcur;                               // stays 0 between calls
__device__ __align__(16) __half d_t[(size_t)N_NODES * 128];   // fp16 gather buffer
__device__ __align__(16) float  d_h[(size_t)N_NODES * 128];

// ---------------- packed f32x2 helpers ----------------
__device__ __forceinline__ unsigned long long pk2(float x) {
    unsigned long long r;
    asm("mov.b64 %0, {%1, %1};" : "=l"(r) : "r"(__float_as_uint(x)));
    return r;
}
#define FMA2(acc, a, b) \
    asm("fma.rn.f32x2 %0, %1, %2, %0;" : "+l"(acc) : "l"(a), "l"(b))
#define MUL2(d, a, b) \
    asm("mul.rn.f32x2 %0, %1, %2;" : "=l"(d) : "l"(a), "l"(b))

__device__ __forceinline__ uint32_t h2_from_u64(unsigned long long v) {
    float2 f;
    asm("mov.b64 {%0, %1}, %2;" : "=f"(f.x), "=f"(f.y) : "l"(v));
    __half2 h = __float22half2_rn(f);
    return *reinterpret_cast<uint32_t*>(&h);
}

// ---------------- CSR build (scan-free) ----------------
__global__ void count_kernel(const int* __restrict__ col, int* __restrict__ cnt) {
    int e2 = blockIdx.x * blockDim.x + threadIdx.x;
    int e = e2 * 2;
    if (e + 1 < N_EDGES) {
        int2 c = *reinterpret_cast<const int2*>(col + e);
        if ((unsigned)c.x < N_NODES) atomicAdd(cnt + c.x, 1);
        if ((unsigned)c.y < N_NODES) atomicAdd(cnt + c.y, 1);
    } else if (e < N_EDGES) {
        unsigned c = (unsigned)col[e];
        if (c < N_NODES) atomicAdd(cnt + c, 1);
    }
}

__global__ void assign_kernel(const int* __restrict__ cnt, int* __restrict__ off,
                              int* __restrict__ cursor, float* __restrict__ dinv,
                              int* __restrict__ gcur) {
    __shared__ int ws[32];
    __shared__ int s_base;
    int i = blockIdx.x * 1024 + threadIdx.x;
    int lane = threadIdx.x & 31, wid = threadIdx.x >> 5;
    int v = (i < N_NODES) ? cnt[i] : 0;
    int x = v;
    #pragma unroll
    for (int d = 1; d < 32; d <<= 1) {
        int y = __shfl_up_sync(0xffffffffu, x, d);
        if (lane >= d) x += y;
    }
    if (lane == 31) ws[wid] = x;
    __syncthreads();
    if (wid == 0) {
        int s = ws[lane];
        #pragma unroll
        for (int d = 1; d < 32; d <<= 1) {
            int y = __shfl_up_sync(0xffffffffu, s, d);
            if (lane >= d) s += y;
        }
        ws[lane] = s;
        if (lane == 31) s_base = atomicAdd(gcur, s);
    }
    __syncthreads();
    int excl = s_base + (wid ? ws[wid - 1] : 0) + x - v;
    if (i < N_NODES) {
        off[i] = excl;
        cursor[i] = excl;
        dinv[i] = rsqrtf((float)(v + 1));
    }
}

__global__ void fill_kernel(const int* __restrict__ row,
                            const int* __restrict__ col,
                            int* __restrict__ cursor, int* __restrict__ src) {
    int e2 = blockIdx.x * blockDim.x + threadIdx.x;
    int e = e2 * 2;
    if (e + 1 < N_EDGES) {
        int2 c = *reinterpret_cast<const int2*>(col + e);
        int2 r = *reinterpret_cast<const int2*>(row + e);
        if ((unsigned)c.x < N_NODES) {
            int pos = atomicAdd(cursor + c.x, 1);
            if ((unsigned)pos < N_EDGES) src[pos] = r.x;
        }
        if ((unsigned)c.y < N_NODES) {
            int pos = atomicAdd(cursor + c.y, 1);
            if ((unsigned)pos < N_EDGES) src[pos] = r.y;
        }
    } else if (e < N_EDGES) {
        unsigned c = (unsigned)col[e];
        if (c < N_NODES) {
            int pos = atomicAdd(cursor + c, 1);
            if ((unsigned)pos < N_EDGES) src[pos] = row[e];
        }
    }
}

// ---------------- GEMM: T[v] = half( dinv[v] * (A[v] @ W) ) ----------------
// BM=128 rows/CTA, 128 threads, W resident in smem, A streamed in BK=32 chunks.
// NOUT=128: thread tile 16x8 (FMA:LDS demand 10.7:1 > 8:1 capacity -> FMA-bound).
// NOUT=64 : thread tile 8x8 (balanced), 48KB smem -> 3-4 CTAs/SM.
template <int NOUT>
__global__ void __launch_bounds__(128, 2)
gemm_kernel(const float* __restrict__ A, const float* __restrict__ W,
            const float* __restrict__ dinv, __half* __restrict__ T) {
    constexpr int RT = (NOUT == 128) ? 16 : 8;   // rows per thread
    constexpr int CG = NOUT / 8;                 // col groups
    extern __shared__ __align__(16) float smem[];
    float* Ws = smem;                            // [128][NOUT]
    float* As = smem + 128 * NOUT;               // [32][128] k-major chunk
    int tid = threadIdx.x;
    int row0 = blockIdx.x * 128;

    // load W once
    for (int i = tid; i < 128 * NOUT / 4; i += 128)
        reinterpret_cast<float4*>(Ws)[i] = reinterpret_cast<const float4*>(W)[i];

    int tx = tid % CG, ty = tid / CG;
    int c0 = tx * 8, r0 = ty * RT;

    unsigned long long acc[RT][4];
    #pragma unroll
    for (int i = 0; i < RT; i++)
        #pragma unroll
        for (int p = 0; p < 4; p++) acc[i][p] = 0ULL;

    // A chunk prefetch: thread owns row (row0+tid), loads its 32 k-values
    const float* arow = A + (size_t)(row0 + tid) * 128;
    bool rv = (row0 + tid) < N_NODES;
    float4 pre[8];
    #pragma unroll
    for (int j = 0; j < 8; j++)
        pre[j] = rv ? *reinterpret_cast<const float4*>(arow + j * 4)
                    : make_float4(0.f, 0.f, 0.f, 0.f);

    #pragma unroll
    for (int ch = 0; ch < 4; ch++) {
        __syncthreads();    // As free (first iter also orders W writes)
        #pragma unroll
        for (int j = 0; j < 8; j++) {
            int kb = j * 4;
            As[(kb + 0) * 128 + tid] = pre[j].x;
            As[(kb + 1) * 128 + tid] = pre[j].y;
            As[(kb + 2) * 128 + tid] = pre[j].z;
            As[(kb + 3) * 128 + tid] = pre[j].w;
        }
        __syncthreads();
        if (ch < 3) {
            const float* nsrc = arow + (ch + 1) * 32;
            #pragma unroll
            for (int j = 0; j < 8; j++)
                pre[j] = rv ? *reinterpret_cast<const float4*>(nsrc + j * 4)
                            : make_float4(0.f, 0.f, 0.f, 0.f);
        }
        const float* wch = Ws + ch * 32 * NOUT + c0;
        #pragma unroll 4
        for (int k = 0; k < 32; k++) {
            const float* ar = As + k * 128 + r0;
            unsigned long long ap[RT];
            #pragma unroll
            for (int q = 0; q < RT / 4; q++) {
                float4 a4 = *reinterpret_cast<const float4*>(ar + q * 4);
                ap[q * 4 + 0] = pk2(a4.x);
                ap[q * 4 + 1] = pk2(a4.y);
                ap[q * 4 + 2] = pk2(a4.z);
                ap[q * 4 + 3] = pk2(a4.w);
            }
            const float* wr = wch + k * NOUT;
            ulonglong2 u0 = *reinterpret_cast<const ulonglong2*>(wr);
            ulonglong2 u1 = *reinterpret_cast<const ulonglong2*>(wr + 4);
            #pragma unroll
            for (int i = 0; i < RT; i++) {
                FMA2(acc[i][0], ap[i], u0.x);
                FMA2(acc[i][1], ap[i], u0.y);
                FMA2(acc[i][2], ap[i], u1.x);
                FMA2(acc[i][3], ap[i], u1.y);
            }
        }
    }

    // epilogue: scale by dinv, convert to half, store 8 halves (16B) per row
    #pragma unroll
    for (int i = 0; i < RT; i++) {
        int r = row0 + r0 + i;
        if (r < N_NODES) {
            unsigned long long dvp = pk2(dinv[r]);
            uint4 o;
            unsigned long long m;
            MUL2(m, acc[i][0], dvp); o.x = h2_from_u64(m);
            MUL2(m, acc[i][1], dvp); o.y = h2_from_u64(m);
            MUL2(m, acc[i][2], dvp); o.z = h2_from_u64(m);
            MUL2(m, acc[i][3], dvp); o.w = h2_from_u64(m);
            *reinterpret_cast<uint4*>(T + (size_t)r * NOUT + c0) = o;
        }
    }
}

// ---------------- aggregation: h[v] = relu(dinv[v]*(t[v] + sum_in t[src]) + b) ----------------
template <int F>
__global__ void agg_kernel(const __half* __restrict__ T,
                           const int* __restrict__ off,
                           const int* __restrict__ cnt,
                           const float* __restrict__ dinv,
                           const float* __restrict__ bias,
                           float* __restrict__ H,
                           const int* __restrict__ src) {
    constexpr int V = F / 32;                 // 4 or 2 halves per lane
    int warp = threadIdx.x >> 5, lane = threadIdx.x & 31;
    int v = blockIdx.x * (blockDim.x >> 5) + warp;
    if (v >= N_NODES) return;
    int f0 = lane * V;
    float acc[V];
    {
        const __half* tv = T + (size_t)v * F + f0;
        if (V == 4) {
            uint2 q = *reinterpret_cast<const uint2*>(tv);
            float2 a = __half22float2(*reinterpret_cast<const __half2*>(&q.x));
            float2 b = __half22float2(*reinterpret_cast<const __half2*>(&q.y));
            acc[0] = a.x; acc[1] = a.y; acc[2] = b.x; acc[3] = b.y;
        } else {
            uint32_t q = *reinterpret_cast<const uint32_t*>(tv);
            float2 a = __half22float2(*reinterpret_cast<const __half2*>(&q));
            acc[0] = a.x; acc[1] = a.y;
        }
    }
    int e0 = off[v], e1 = e0 + cnt[v];
    #pragma unroll 4
    for (int e = e0; e < e1; e++) {
        int s = src[e];
        const __half* ts = T + (size_t)s * F + f0;
        if (V == 4) {
            uint2 q = *reinterpret_cast<const uint2*>(ts);
            float2 a = __half22float2(*reinterpret_cast<const __half2*>(&q.x));
            float2 b = __half22float2(*reinterpret_cast<const __half2*>(&q.y));
            acc[0] += a.x; acc[1] += a.y; acc[2] += b.x; acc[3] += b.y;
        } else {
            uint32_t q = *reinterpret_cast<const uint32_t*>(ts);
            float2 a = __half22float2(*reinterpret_cast<const __half2*>(&q));
            acc[0] += a.x; acc[1] += a.y;
        }
    }
    float dv = dinv[v];
    float* hv = H + (size_t)v * F + f0;
    #pragma unroll
    for (int i = 0; i < V; i++) {
        float o = dv * acc[i] + bias[f0 + i];
        hv[i] = fmaxf(o, 0.f);
    }
}

// ---------------- pooling + MLP (+ cleanup of cnt/gcur for next call) ----------------
__device__ __forceinline__ int lb32(const int* __restrict__ b, int n, int key) {
    int lo = 0, hi = n;
    while (lo < hi) {
        int mid = (lo + hi) >> 1;
        if (b[mid] < key) lo = mid + 1; else hi = mid;
    }
    return lo;
}

__global__ void pool_mlp_kernel(const float* __restrict__ H,
                                const int* __restrict__ batch,
                                const float* __restrict__ Wf1, const float* __restrict__ bf1,
                                const float* __restrict__ Wf2, const float* __restrict__ bf2,
                                float* __restrict__ out,
                                int* __restrict__ cnt, int* __restrict__ gcur) {
    __shared__ float partial[256];
    __shared__ float pooled[64];
    __shared__ float hid[32];
    int g = blockIdx.x;
    int t = threadIdx.x;
    for (int i = g * 256 + t; i < N_NODES; i += N_GRAPHS * 256) cnt[i] = 0;
    if (g == 0 && t == 0) *gcur = 0;

    int start = lb32(batch, N_NODES, g);
    int end   = lb32(batch, N_NODES, g + 1);
    int n = end - start;
    int feat = t & 63;
    int strip = t >> 6;
    float s = 0.f;
    for (int i = start + strip; i < end; i += 4)
        s += H[(size_t)i * 64 + feat];
    partial[t] = s;
    __syncthreads();
    if (t < 64) {
        float tot = partial[t] + partial[t + 64] + partial[t + 128] + partial[t + 192];
        pooled[t] = tot / fmaxf((float)n, 1.0f);
    }
    __syncthreads();
    if (t < 32) {
        float a = bf1[t];
        #pragma unroll 8
        for (int k = 0; k < 64; k++) a += pooled[k] * Wf1[k * 32 + t];
        hid[t] = fmaxf(a, 0.f);
    }
    __syncthreads();
    if (t < 10) {
        float a = bf2[t];
        #pragma unroll
        for (int k = 0; k < 32; k++) a += hid[k] * Wf2[k * 10 + t];
        out[g * 10 + t] = a;
    }
}

// ---------------- launch ----------------
extern "C" void kernel_launch(void* const* d_in, const int* in_sizes, int n_in,
                              void* d_out, int out_size) {
    const float* x     = (const float*)d_in[0];
    const int*   ei    = (const int*)d_in[1];     // int32 (JAX x64 disabled)
    const int*   batch = (const int*)d_in[2];
    const float* W1 = (const float*)d_in[3];
    const float* b1 = (const float*)d_in[4];
    const float* W2 = (const float*)d_in[5];
    const float* b2 = (const float*)d_in[6];
    const float* W3 = (const float*)d_in[7];
    const float* b3 = (const float*)d_in[8];
    const float* Wf1 = (const float*)d_in[9];
    const float* bf1 = (const float*)d_in[10];
    const float* Wf2 = (const float*)d_in[11];
    const float* bf2 = (const float*)d_in[12];
    float* out = (float*)d_out;

    const int* row = ei;
    const int* col = ei + N_EDGES;

    int *p_cnt, *p_off, *p_cursor, *p_src, *p_gcur;
    float *p_dinv, *p_h;
    __half* p_t;
    cudaGetSymbolAddress((void**)&p_cnt,    d_cnt);
    cudaGetSymbolAddress((void**)&p_off,    d_off);
    cudaGetSymbolAddress((void**)&p_cursor, d_cursor);
    cudaGetSymbolAddress((void**)&p_src,    d_src);
    cudaGetSymbolAddress((void**)&p_gcur,   d_gcur);
    cudaGetSymbolAddress((void**)&p_dinv,   d_dinv);
    cudaGetSymbolAddress((void**)&p_t,      d_t);
    cudaGetSymbolAddress((void**)&p_h,      d_h);

    const int SM128 = (128 * 128 + 32 * 128) * 4;   // 80 KB
    const int SM64  = (128 * 64  + 32 * 128) * 4;   // 48 KB
    cudaFuncSetAttribute(gemm_kernel<128>, cudaFuncAttributeMaxDynamicSharedMemorySize, SM128);
    cudaFuncSetAttribute(gemm_kernel<64>,  cudaFuncAttributeMaxDynamicSharedMemorySize, SM64);

    const int E2 = (N_EDGES / 2 + 255) / 256;
    const int GB = (N_NODES + 127) / 128;    // 391
    const int AGG_BLOCKS = (N_NODES + 7) / 8;

    // CSR build
    count_kernel<<<E2, 256>>>(col, p_cnt);                                           // 1
    assign_kernel<<<(N_NODES + 1023) / 1024, 1024>>>(p_cnt, p_off, p_cursor, p_dinv, p_gcur); // 2
    fill_kernel<<<E2, 256>>>(row, col, p_cursor, p_src);                             // 3

    gemm_kernel<128><<<GB, 128, SM128>>>(x, W1, p_dinv, p_t);                        // 4
    agg_kernel<128><<<AGG_BLOCKS, 256>>>(p_t, p_off, p_cnt, p_dinv, b1, p_h, p_src); // 5
    gemm_kernel<128><<<GB, 128, SM128>>>(p_h, W2, p_dinv, p_t);                      // 6 <- ncu
    agg_kernel<128><<<AGG_BLOCKS, 256>>>(p_t, p_off, p_cnt, p_dinv, b2, p_h, p_src); // 7
    gemm_kernel<64><<<GB, 128, SM64>>>(p_h, W3, p_dinv, p_t);                        // 8
    agg_kernel<64><<<AGG_BLOCKS, 256>>>(p_t, p_off, p_cnt, p_dinv, b3, p_h, p_src);  // 9

    pool_mlp_kernel<<<N_GRAPHS, 256>>>(p_h, batch, Wf1, bf1, Wf2, bf2, out, p_cnt, p_gcur); // 10
}